// round 3
// baseline (speedup 1.0000x reference)
#include <cuda_runtime.h>
#include <cuda_bf16.h>
#include <mma.h>

using namespace nvcuda;

// Problem constants (fixed by the dataset)
#define M_MAX   8192
#define K_DIM   4096
#define N_DIM   4096
#define NBASIS  256

// Scratch (static device arrays — no allocation allowed)
__device__ __nv_bfloat16 g_Xhi[M_MAX * K_DIM];
__device__ __nv_bfloat16 g_Xlo[M_MAX * K_DIM];
__device__ __nv_bfloat16 g_Wres[N_DIM * K_DIM];
__device__ __nv_bfloat16 g_Bhi[NBASIS * K_DIM];
__device__ __nv_bfloat16 g_Blo[NBASIS * K_DIM];
__device__ float         g_P[M_MAX * NBASIS];

// ---------------------------------------------------------------------------
// Prep kernels
// ---------------------------------------------------------------------------

__global__ void prep_x(const float* __restrict__ x,
                       __nv_bfloat16* __restrict__ hi,
                       __nv_bfloat16* __restrict__ lo, int n4) {
    int i = blockIdx.x * blockDim.x + threadIdx.x;
    if (i >= n4) return;
    float4 v = ((const float4*)x)[i];
    __nv_bfloat162 h01 = __floats2bfloat162_rn(v.x, v.y);
    __nv_bfloat162 h23 = __floats2bfloat162_rn(v.z, v.w);
    ((__nv_bfloat162*)hi)[2 * i]     = h01;
    ((__nv_bfloat162*)hi)[2 * i + 1] = h23;
    float l0 = v.x - __bfloat162float(h01.x);
    float l1 = v.y - __bfloat162float(h01.y);
    float l2 = v.z - __bfloat162float(h23.x);
    float l3 = v.w - __bfloat162float(h23.y);
    ((__nv_bfloat162*)lo)[2 * i]     = __floats2bfloat162_rn(l0, l1);
    ((__nv_bfloat162*)lo)[2 * i + 1] = __floats2bfloat162_rn(l2, l3);
}

__global__ void prep_w(const int* __restrict__ q,
                       __nv_bfloat16* __restrict__ w, int n4) {
    int i = blockIdx.x * blockDim.x + threadIdx.x;
    if (i >= n4) return;
    int4 v = ((const int4*)q)[i];
    // q - 128 is an integer in [-128,127]: exactly representable in bf16.
    __nv_bfloat162 w01 = __floats2bfloat162_rn((float)(v.x - 128), (float)(v.y - 128));
    __nv_bfloat162 w23 = __floats2bfloat162_rn((float)(v.z - 128), (float)(v.w - 128));
    ((__nv_bfloat162*)w)[2 * i]     = w01;
    ((__nv_bfloat162*)w)[2 * i + 1] = w23;
}

// ---------------------------------------------------------------------------
// bf16 GEMM: C[M, ldc] = sum over passes of A_p @ B_p^T   (A,B both K-major)
// CTA tile 128x128x32, 8 warps (2x4), warp tile 64x32, wmma 16x16x16,
// cp.async double-buffered shared memory.
// ---------------------------------------------------------------------------

#define BM 128
#define BN 128
#define BK 32
#define SSTRIDE 40   // 32 + 8 pad (bf16) -> 80B rows, conflict-free ldmatrix

__device__ __forceinline__ void cpasync16(void* smem, const void* gmem) {
    unsigned saddr = (unsigned)__cvta_generic_to_shared(smem);
    asm volatile("cp.async.cg.shared.global [%0], [%1], 16;\n"
                 :: "r"(saddr), "l"(gmem));
}
__device__ __forceinline__ void cpcommit() {
    asm volatile("cp.async.commit_group;\n");
}
__device__ __forceinline__ void cpwait0() {
    asm volatile("cp.async.wait_group 0;\n");
}

__global__ __launch_bounds__(256)
void gemm_bf16(const __nv_bfloat16* __restrict__ A0, const __nv_bfloat16* __restrict__ B0,
               const __nv_bfloat16* __restrict__ A1, const __nv_bfloat16* __restrict__ B1,
               const __nv_bfloat16* __restrict__ A2, const __nv_bfloat16* __restrict__ B2,
               int npasses, float* __restrict__ C, int K, int ldc) {
    __shared__ __nv_bfloat16 As[2][BM][SSTRIDE];
    __shared__ __nv_bfloat16 Bs[2][BN][SSTRIDE];

    int tid  = threadIdx.x;
    int warp = tid >> 5;
    int wm   = warp >> 2;   // 0..1
    int wn   = warp & 3;    // 0..3

    size_t mBase = (size_t)blockIdx.y * BM;
    size_t nBase = (size_t)blockIdx.x * BN;

    wmma::fragment<wmma::accumulator, 16, 16, 16, float> acc[4][2];
#pragma unroll
    for (int i = 0; i < 4; i++)
#pragma unroll
        for (int j = 0; j < 2; j++) wmma::fill_fragment(acc[i][j], 0.0f);

    const __nv_bfloat16* APs[3] = {A0, A1, A2};
    const __nv_bfloat16* BPs[3] = {B0, B1, B2};

    int KT = K / BK;

    for (int pass = 0; pass < npasses; pass++) {
        const __nv_bfloat16* A = APs[pass];
        const __nv_bfloat16* B = BPs[pass];

        // Prologue: load tile 0 into buffer 0
#pragma unroll
        for (int it = 0; it < 2; it++) {
            int cid = tid + it * 256;
            int r = cid >> 2;
            int c = (cid & 3) * 8;
            cpasync16(&As[0][r][c], A + (mBase + r) * K + c);
            cpasync16(&Bs[0][r][c], B + (nBase + r) * K + c);
        }
        cpcommit();

        for (int kt = 0; kt < KT; kt++) {
            cpwait0();
            __syncthreads();

            if (kt + 1 < KT) {
                int kOff = (kt + 1) * BK;
                int nbuf = (kt + 1) & 1;
#pragma unroll
                for (int it = 0; it < 2; it++) {
                    int cid = tid + it * 256;
                    int r = cid >> 2;
                    int c = (cid & 3) * 8;
                    cpasync16(&As[nbuf][r][c], A + (mBase + r) * K + kOff + c);
                    cpasync16(&Bs[nbuf][r][c], B + (nBase + r) * K + kOff + c);
                }
                cpcommit();
            }

            int buf = kt & 1;
#pragma unroll
            for (int ks = 0; ks < 2; ks++) {
                wmma::fragment<wmma::matrix_a, 16, 16, 16, __nv_bfloat16, wmma::row_major> af[4];
                wmma::fragment<wmma::matrix_b, 16, 16, 16, __nv_bfloat16, wmma::col_major> bf[2];
#pragma unroll
                for (int i = 0; i < 4; i++)
                    wmma::load_matrix_sync(af[i], &As[buf][wm * 64 + i * 16][ks * 16], SSTRIDE);
#pragma unroll
                for (int j = 0; j < 2; j++)
                    wmma::load_matrix_sync(bf[j], &Bs[buf][wn * 32 + j * 16][ks * 16], SSTRIDE);
#pragma unroll
                for (int i = 0; i < 4; i++)
#pragma unroll
                    for (int j = 0; j < 2; j++)
                        wmma::mma_sync(acc[i][j], af[i], bf[j], acc[i][j]);
            }
        }
    }

#pragma unroll
    for (int i = 0; i < 4; i++)
#pragma unroll
        for (int j = 0; j < 2; j++)
            wmma::store_matrix_sync(
                C + (mBase + wm * 64 + i * 16) * (size_t)ldc + nBase + wn * 32 + j * 16,
                acc[i][j], ldc, wmma::mem_row_major);
}

// ---------------------------------------------------------------------------
// Epilogue: y = sp[o]*Q + r[o]*P[m, idx[o]] + bias[o]   (in place over d_out)
// ---------------------------------------------------------------------------

__global__ void epilogue(float* __restrict__ y, const float* __restrict__ P,
                         const int* __restrict__ codes,
                         const float* __restrict__ scales,
                         const float* __restrict__ bias, int total, int N) {
    int i = blockIdx.x * blockDim.x + threadIdx.x;
    if (i >= total) return;
    unsigned ui = (unsigned)i;
    unsigned m = ui / (unsigned)N;
    unsigned o = ui - m * (unsigned)N;
    int code = codes[o];
    int idx = code & 0xFF;
    float r  = (float)((code >> 8) & 0xFFFF) * (1.0f / 65535.0f);
    float sp = scales[o] * (1.0f / 127.0f);
    y[i] = sp * y[i] + r * __ldg(&P[(size_t)m * NBASIS + idx]) + bias[o];
}

// ---------------------------------------------------------------------------
// Launch
// ---------------------------------------------------------------------------

extern "C" void kernel_launch(void* const* d_in, const int* in_sizes, int n_in,
                              void* d_out, int out_size) {
    const float* x      = (const float*)d_in[0];
    const int*   codes  = (const int*)d_in[1];
    const float* basis  = (const float*)d_in[2];
    const int*   residq = (const int*)d_in[3];
    const float* scales = (const float*)d_in[4];
    const float* bias   = (const float*)d_in[5];
    float*       y      = (float*)d_out;

    int N = in_sizes[1];                 // 4096
    int K = in_sizes[2] / NBASIS;        // 4096
    int M = in_sizes[0] / K;             // 8192

    __nv_bfloat16 *Xhi, *Xlo, *Wres, *Bhi, *Blo;
    float* P;
    cudaGetSymbolAddress((void**)&Xhi,  g_Xhi);
    cudaGetSymbolAddress((void**)&Xlo,  g_Xlo);
    cudaGetSymbolAddress((void**)&Wres, g_Wres);
    cudaGetSymbolAddress((void**)&Bhi,  g_Bhi);
    cudaGetSymbolAddress((void**)&Blo,  g_Blo);
    cudaGetSymbolAddress((void**)&P,    g_P);

    // 1) Preprocess: split x into bf16 hi/lo; residual -> exact bf16 ints;
    //    basis -> bf16 hi/lo.
    int nx4 = (M * K) / 4;
    prep_x<<<(nx4 + 255) / 256, 256>>>(x, Xhi, Xlo, nx4);
    int nw4 = (N * K) / 4;
    prep_w<<<(nw4 + 255) / 256, 256>>>(residq, Wres, nw4);
    int nb4 = (NBASIS * K) / 4;
    prep_x<<<(nb4 + 255) / 256, 256>>>(basis, Bhi, Blo, nb4);

    // 2) Small GEMM: P[M,256] = Xhi*Bhi^T + Xhi*Blo^T + Xlo*Bhi^T (split-bf16)
    gemm_bf16<<<dim3(NBASIS / BN, M / BM), 256>>>(
        Xhi, Bhi, Xhi, Blo, Xlo, Bhi, 3, P, K, NBASIS);

    // 3) Big GEMM: Q[M,N] = Xhi * Wres^T (weights are exact integers in bf16)
    //    -> raw accumulator stored in d_out
    gemm_bf16<<<dim3(N / BN, M / BM), 256>>>(
        Xhi, Wres, Xhi, Wres, Xhi, Wres, 1, y, K, N);

    // 4) Fused epilogue: y = sp*Q + r*P[m,idx] + bias   (in place)
    int total = M * N;
    epilogue<<<(total + 255) / 256, 256>>>(y, P, codes, scales, bias, total, N);
}